// round 15
// baseline (speedup 1.0000x reference)
#include <cuda_runtime.h>

// Problem constants: B=16, N=8192, C=128, H=2, hd=64, G=2
#define NB 16
#define NN 8192
#define LPB 64             // 128-row slots per b (fused: 1 block = 1 slot)

// Scratch (device globals — no allocation allowed)
__device__ float g_u[2 * 128];                 // folded mem·Wk·scale  [h][cin]
__device__ float g_num[NB * 2 * LPB * 128];    // per-slot partial Σ e·x (1 MB)
__device__ float g_den[NB * 2 * LPB];          // per-slot partial Σ e

// ---------------------------------------------------------------------------
// Kernel 1: u[h, g*64+i] = scale * sum_j mem[h, 2j+g] * Wk[g, h*32+j, i]
// Wk staged via coalesced float4 loads (R10 lesson: strided cold loads are 5x
// slower). Hidden under k_fused's pre-issued x loads via PDL.
// ---------------------------------------------------------------------------
__global__ void k_prep_u(const float* __restrict__ Wk, const float* __restrict__ mem) {
    __shared__ float sW[8192];
    __shared__ float sm[128];
    int t = threadIdx.x;                // 256 threads

    float4* sW4 = (float4*)sW;
    const float4* gW4 = (const float4*)Wk;
#pragma unroll
    for (int k = 0; k < 8; ++k)
        sW4[t + 256 * k] = __ldg(gW4 + t + 256 * k);
    if (t < 128) sm[t] = mem[t];
    __syncthreads();

    int h = t >> 7, cin = t & 127, g = cin >> 6, i = cin & 63;
    float acc = 0.f;
#pragma unroll
    for (int j = 0; j < 32; ++j)
        acc += sm[h * 64 + 2 * j + g] * sW[(g * 64 + h * 32 + j) * 64 + i];
    g_u[t] = acc * 0.125f;              // scale = hd^-0.5 = 1/8
    __threadfence();
    cudaTriggerProgrammaticLaunchCompletion();
}

// ---------------------------------------------------------------------------
// Kernel 2 (FUSED): the proven R8 register-butterfly loop, 16 warps/block.
// Each warp owns 8 rows end-to-end; block owns 128 rows. grid = 1024 x 512.
// Writes ONE partial per (b,h,slot) -> only 64 partials per (b,h).
// ---------------------------------------------------------------------------
__global__ __launch_bounds__(512) void k_fused(const float* __restrict__ x) {
    __shared__ float4 sacc[2][16][32];
    __shared__ float  sden[2][16];

    int t = threadIdx.x, w = t >> 5, lane = t & 31;
    int b = blockIdx.x >> 6;
    int l = blockIdx.x & (LPB - 1);     // slot: rows [l*128, l*128+128)

    const float4* xb = (const float4*)x
        + ((size_t)b * NN + (size_t)l * 128 + (size_t)w * 8) * 32 + lane;
    float4 v[8];
#pragma unroll
    for (int k = 0; k < 8; ++k) v[k] = __ldcs(xb + k * 32);   // pre-sync work

    cudaGridDependencySynchronize();     // g_u ready (PDL edge from k_prep_u)

    float4 u0 = ((const float4*)g_u)[lane];        // L2-hot
    float4 u1 = ((const float4*)g_u)[32 + lane];

    float4 a0 = make_float4(0.f, 0.f, 0.f, 0.f);
    float4 a1 = make_float4(0.f, 0.f, 0.f, 0.f);
    float den0 = 0.f, den1 = 0.f;
    bool odd = lane & 1;

#pragma unroll
    for (int k = 0; k < 8; ++k) {
        float4 xv = v[k];
        float p0 = xv.x * u0.x + xv.y * u0.y + xv.z * u0.z + xv.w * u0.w;
        float p1 = xv.x * u1.x + xv.y * u1.y + xv.z * u1.z + xv.w * u1.w;
        // folded reduction: level-1 pair sums, parity select, xor tree, swap
        float aa = p0 + __shfl_xor_sync(0xffffffffu, p0, 1);
        float bb = p1 + __shfl_xor_sync(0xffffffffu, p1, 1);
        float c = odd ? bb : aa;            // even lanes carry h0, odd h1
        c += __shfl_xor_sync(0xffffffffu, c, 2);
        c += __shfl_xor_sync(0xffffffffu, c, 4);
        c += __shfl_xor_sync(0xffffffffu, c, 8);
        c += __shfl_xor_sync(0xffffffffu, c, 16);
        float d = __shfl_xor_sync(0xffffffffu, c, 1);
        float s0 = odd ? d : c;
        float s1 = odd ? c : d;
        float e0 = __expf(s0);              // no max shift; logits are O(1)
        float e1 = __expf(s1);
        a0.x += e0 * xv.x; a0.y += e0 * xv.y; a0.z += e0 * xv.z; a0.w += e0 * xv.w;
        a1.x += e1 * xv.x; a1.y += e1 * xv.y; a1.z += e1 * xv.z; a1.w += e1 * xv.w;
        den0 += e0; den1 += e1;             // identical in all lanes
    }

    sacc[0][w][lane] = a0;
    sacc[1][w][lane] = a1;
    if (lane == 0) { sden[0][w] = den0; sden[1][w] = den1; }
    __syncthreads();

    if (t < 64) {
        int h = t >> 5, c = t & 31;
        float4 r = sacc[h][0][c];
#pragma unroll
        for (int ww = 1; ww < 16; ++ww) {
            float4 p = sacc[h][ww][c];
            r.x += p.x; r.y += p.y; r.z += p.z; r.w += p.w;
        }
        ((float4*)g_num)[((size_t)(b * 2 + h) * LPB + l) * 32 + c] = r;
    } else if (t < 66) {
        int h = t - 64;
        float dsum = 0.f;
#pragma unroll
        for (int ww = 0; ww < 16; ++ww) dsum += sden[h][ww];
        g_den[(size_t)(b * 2 + h) * LPB + l] = dsum;
    }
    __threadfence();
    cudaTriggerProgrammaticLaunchCompletion();
}

// ---------------------------------------------------------------------------
// Kernel 3 (FINALIZE + BROADCAST merged): 512 blocks x 256 threads.
// Block (bh, seg): redundantly reduce own (b,h)'s 64x128 partials from L2
// (coalesced, MLP-rich), tiny Wv/Wp GEMV chain in smem, then write its
// 256-row output segment (32 coalesced streaming STG.128 per thread).
// ---------------------------------------------------------------------------
__global__ __launch_bounds__(256) void k_out(const float* __restrict__ Wv,
                                             const float* __restrict__ Wp,
                                             const float* __restrict__ bp,
                                             float4* __restrict__ out) {
    __shared__ float sd[LPB];
    __shared__ float xa[128];
    __shared__ float rowv[64];
    __shared__ __align__(16) float sfv[128];

    int t = threadIdx.x;
    int bh = blockIdx.x >> 4;           // 0..31 = b*2 + h
    int seg = blockIdx.x & 15;          // 16 segments of 256 rows each
    int h = bh & 1;

    cudaGridDependencySynchronize();    // g_num/g_den ready

    if (t < 128) {                      // numerator reduce: 64 coalesced loads
        const float* np = g_num + (size_t)bh * LPB * 128;
        float s = 0.f;
#pragma unroll
        for (int j = 0; j < LPB; ++j) s += np[(size_t)j * 128 + t];
        xa[t] = s;                      // divide after den ready
    } else if (t < 192) {
        sd[t - 128] = g_den[(size_t)bh * LPB + (t - 128)];
    }
    __syncthreads();

    if (t < 128) {                      // fixed-order den sum (deterministic)
        float d = 0.f;
#pragma unroll
        for (int j = 0; j < LPB; ++j) d += sd[j];
        xa[t] = xa[t] / d;
    }
    __syncthreads();

    if (t < 64) {   // rowv[d] = Σ_i xa[g*64+i] · Wv[g, h*32+d/2, i],  g = d%2
        int g = t & 1, o = h * 32 + (t >> 1);
        const float* wv = Wv + (g * 64 + o) * 64;
        const float* xv = xa + g * 64;
        float acc = 0.f;
#pragma unroll
        for (int i = 0; i < 64; ++i) acc += xv[i] * wv[i];
        rowv[t] = acc;
    }
    __syncthreads();

    if (t < 128) {  // sfv[c2] = bp[g2,o2] + Σ_i rowv[i] · Wp[g2,o2,i]
        int g2 = t & 1, o2 = t >> 1;
        const float* wp = Wp + (g2 * 64 + o2) * 64;
        float f = bp[g2 * 64 + o2];
#pragma unroll
        for (int i = 0; i < 64; ++i) f += rowv[i] * wp[i];
        sfv[t] = f;
    }
    __syncthreads();

    // write own 256-row segment: 8192 float4, 32 STG.128/thread, coalesced
    float4 vv = ((const float4*)sfv)[t & 31];
    float4* dst = out + (size_t)bh * 131072 + (size_t)seg * 8192;
#pragma unroll 8
    for (int k = 0; k < 32; ++k)
        __stcs(dst + k * 256 + t, vv);  // (k*256+t)%32 == t%32 -> channel ok
}

// ---------------------------------------------------------------------------
extern "C" void kernel_launch(void* const* d_in, const int* in_sizes, int n_in,
                              void* d_out, int out_size) {
    const float* x   = (const float*)d_in[0];
    const float* Wk  = (const float*)d_in[1];
    const float* Wv  = (const float*)d_in[2];
    const float* Wp  = (const float*)d_in[3];
    const float* bp  = (const float*)d_in[4];
    const float* mem = (const float*)d_in[5];
    float4* out = (float4*)d_out;

    k_prep_u<<<1, 256>>>(Wk, mem);

    cudaLaunchAttribute at[1];
    at[0].id = cudaLaunchAttributeProgrammaticStreamSerialization;
    at[0].val.programmaticStreamSerializationAllowed = 1;

    cudaLaunchConfig_t cfg = {};
    cfg.stream = 0;
    cfg.attrs = at;
    cfg.numAttrs = 1;

    cfg.gridDim = dim3(NB * LPB);      // 1024
    cfg.blockDim = dim3(512);
    cudaLaunchKernelEx(&cfg, k_fused, x);

    cfg.gridDim = dim3(512);
    cfg.blockDim = dim3(256);
    cudaLaunchKernelEx(&cfg, k_out, Wv, Wp, bp, out);
}

// round 17
// speedup vs baseline: 1.4244x; 1.4244x over previous
#include <cuda_runtime.h>

// Problem constants: B=16, N=8192, C=128, H=2, hd=64, G=2
#define NB 16
#define NN 8192
#define NCH 256            // 32-row chunks per b

// Scratch (device globals — no allocation allowed)
__device__ float g_u[2 * 128];                  // folded mem·Wk·scale  [h][cin]
__device__ float g_num[NB * 2 * NCH * 128];     // per-chunk partial Σ e·x (4 MB)
__device__ float g_den[NB * 2 * NCH];           // per-chunk partial Σ e
__device__ float g_fv[NB * 2 * 128];            // final vectors [b][half][c]

// Batched 8-row fold: input q[k] = this lane's partial dot of row k (k=0..7).
// 3 select+shfl fold stages collapse lane bits 0-2 while binding the row
// index to them; 2 xor stages finish the lane sum. Returns the FULL row-sum
// of row (lane & 7). 9 shfl total for 8 rows (vs 7 shfl PER row before).
__device__ __forceinline__ float fold8(const float q[8], int lane) {
    bool b0 = lane & 1, b1 = lane & 2, b2 = lane & 4;
    float r[4];
#pragma unroll
    for (int j = 0; j < 4; ++j) {
        float send = b0 ? q[2 * j] : q[2 * j + 1];
        float keep = b0 ? q[2 * j + 1] : q[2 * j];
        r[j] = keep + __shfl_xor_sync(0xffffffffu, send, 1);   // row 2j+b0
    }
    float s[2];
#pragma unroll
    for (int j = 0; j < 2; ++j) {
        float send = b1 ? r[2 * j] : r[2 * j + 1];
        float keep = b1 ? r[2 * j + 1] : r[2 * j];
        s[j] = keep + __shfl_xor_sync(0xffffffffu, send, 2);   // row 4j+2b1+b0
    }
    float send = b2 ? s[0] : s[1];
    float keep = b2 ? s[1] : s[0];
    float tt = keep + __shfl_xor_sync(0xffffffffu, send, 4);   // row lane&7
    tt += __shfl_xor_sync(0xffffffffu, tt, 8);
    tt += __shfl_xor_sync(0xffffffffu, tt, 16);
    return tt;
}

// ---------------------------------------------------------------------------
// Kernel 1: u[h, g*64+i] = scale * sum_j mem[h, 2j+g] * Wk[g, h*32+j, i]
// ---------------------------------------------------------------------------
__global__ void k_prep_u(const float* __restrict__ Wk, const float* __restrict__ mem) {
    __shared__ float sW[8192];
    __shared__ float sm[128];
    int t = threadIdx.x;                // 256 threads

    float4* sW4 = (float4*)sW;
    const float4* gW4 = (const float4*)Wk;
#pragma unroll
    for (int k = 0; k < 8; ++k)
        sW4[t + 256 * k] = __ldg(gW4 + t + 256 * k);
    if (t < 128) sm[t] = mem[t];
    __syncthreads();

    int h = t >> 7, cin = t & 127, g = cin >> 6, i = cin & 63;
    float acc = 0.f;
#pragma unroll
    for (int j = 0; j < 32; ++j)
        acc += sm[h * 64 + 2 * j + g] * sW[(g * 64 + h * 32 + j) * 64 + i];
    g_u[t] = acc * 0.125f;              // scale = hd^-0.5 = 1/8
    __threadfence();
    cudaTriggerProgrammaticLaunchCompletion();
}

// ---------------------------------------------------------------------------
// Kernel 2 (FUSED, register-only): per-lane partial dots for all 8 rows,
// batched fold8 per head (9 shfl), ONE exp per head per lane, 16 broadcast
// shfl feed the weighted accumulate. 34 shfl + 2 exp per 8 rows vs the old
// 56 shfl + 16 exp, with parallel (not serial) dependency trees.
// grid = 4096 x 128.
// ---------------------------------------------------------------------------
__global__ __launch_bounds__(128) void k_fused(const float* __restrict__ x) {
    __shared__ float4 sacc[2][4][32];
    __shared__ float  sden[2][4];

    int t = threadIdx.x, w = t >> 5, lane = t & 31;
    int b = blockIdx.x >> 8;
    int chunk = blockIdx.x & (NCH - 1);

    const float4* xb = (const float4*)x
        + ((size_t)b * NN + (size_t)chunk * 32 + (size_t)w * 8) * 32 + lane;
    float4 v[8];
#pragma unroll
    for (int k = 0; k < 8; ++k) v[k] = __ldcs(xb + k * 32);   // pre-sync work

    cudaGridDependencySynchronize();     // g_u ready (PDL edge from k_prep_u)

    float4 u0 = ((const float4*)g_u)[lane];        // L2-hot
    float4 u1 = ((const float4*)g_u)[32 + lane];

    // per-lane partial dots for all 8 rows, both heads
    float q0[8], q1[8];
#pragma unroll
    for (int k = 0; k < 8; ++k) {
        float4 xv = v[k];
        q0[k] = xv.x * u0.x + xv.y * u0.y + xv.z * u0.z + xv.w * u0.w;
        q1[k] = xv.x * u1.x + xv.y * u1.y + xv.z * u1.z + xv.w * u1.w;
    }

    // full row-sums (row = lane&7), one exp per head (no max shift; logits
    // are O(1) by construction)
    float e0v = __expf(fold8(q0, lane));
    float e1v = __expf(fold8(q1, lane));

    float4 a0 = make_float4(0.f, 0.f, 0.f, 0.f);
    float4 a1 = make_float4(0.f, 0.f, 0.f, 0.f);
    float den0 = 0.f, den1 = 0.f;

#pragma unroll
    for (int k = 0; k < 8; ++k) {
        float e0 = __shfl_sync(0xffffffffu, e0v, k);   // lane k holds row k
        float e1 = __shfl_sync(0xffffffffu, e1v, k);
        float4 xv = v[k];
        a0.x += e0 * xv.x; a0.y += e0 * xv.y; a0.z += e0 * xv.z; a0.w += e0 * xv.w;
        a1.x += e1 * xv.x; a1.y += e1 * xv.y; a1.z += e1 * xv.z; a1.w += e1 * xv.w;
        den0 += e0; den1 += e1;             // identical in all lanes
    }

    sacc[0][w][lane] = a0;
    sacc[1][w][lane] = a1;
    if (lane == 0) { sden[0][w] = den0; sden[1][w] = den1; }
    __syncthreads();

    if (t < 64) {
        int h = t >> 5, c = t & 31;
        float4 r = sacc[h][0][c];
#pragma unroll
        for (int ww = 1; ww < 4; ++ww) {
            float4 p = sacc[h][ww][c];
            r.x += p.x; r.y += p.y; r.z += p.z; r.w += p.w;
        }
        ((float4*)g_num)[((size_t)(b * 2 + h) * NCH + chunk) * 32 + c] = r;
    } else if (t < 66) {
        int h = t - 64;
        g_den[(size_t)(b * 2 + h) * NCH + chunk]
            = sden[h][0] + sden[h][1] + sden[h][2] + sden[h][3];
    }
    __threadfence();
    cudaTriggerProgrammaticLaunchCompletion();
}

// ---------------------------------------------------------------------------
// Kernel 3: finalize. One block per (b,h): wide parallel chunk reduce (8
// slices x 32), then the tiny Wv/Wp GEMV chain. 32 blocks x 1024 threads.
// ---------------------------------------------------------------------------
__global__ __launch_bounds__(1024) void k_final(const float* __restrict__ Wv,
                                                const float* __restrict__ Wp,
                                                const float* __restrict__ bp) {
    cudaGridDependencySynchronize();     // g_num/g_den ready

    int bh = blockIdx.x, b = bh >> 1, h = bh & 1;
    int t = threadIdx.x;
    __shared__ float sred[8][128];
    __shared__ float sdn[8];
    __shared__ float xa[128];
    __shared__ float row[64];

    int c = t & 127, slice = t >> 7;    // 8 slices x 32 chunks
    const float* base = g_num + (size_t)bh * NCH * 128;
    float a = 0.f;
#pragma unroll
    for (int j = 0; j < 32; ++j)
        a += base[(size_t)(slice * 32 + j) * 128 + c];
    sred[slice][c] = a;

    if (t < 256) {                       // den reduce: 8 full warps
        float d = g_den[(size_t)bh * NCH + t];
#pragma unroll
        for (int off = 16; off > 0; off >>= 1)
            d += __shfl_xor_sync(0xffffffffu, d, off);
        if ((t & 31) == 0) sdn[t >> 5] = d;
    }
    __syncthreads();

    if (t < 128) {
        float s = 0.f;
#pragma unroll
        for (int sl = 0; sl < 8; ++sl) s += sred[sl][t];
        float dd = sdn[0] + sdn[1] + sdn[2] + sdn[3]
                 + sdn[4] + sdn[5] + sdn[6] + sdn[7];
        xa[t] = s / dd;
    }
    __syncthreads();

    if (t < 64) {                        // row[d] = Σ_i xa[g*64+i]·Wv[g,h*32+d/2,i]
        int g = t & 1, o = h * 32 + (t >> 1);
        const float* w = Wv + (g * 64 + o) * 64;
        const float* xv = xa + g * 64;
        float acc = 0.f;
#pragma unroll
        for (int i = 0; i < 64; ++i) acc += xv[i] * w[i];
        row[t] = acc;
    }
    __syncthreads();

    if (t < 128) {                       // fv = row·Wp + bp (half == h)
        int g2 = t & 1, o2 = t >> 1;
        const float* w = Wp + (g2 * 64 + o2) * 64;
        float f = bp[g2 * 64 + o2];
#pragma unroll
        for (int i = 0; i < 64; ++i) f += row[i] * w[i];
        g_fv[(size_t)b * 256 + h * 128 + t] = f;
    }
    __threadfence();
    cudaTriggerProgrammaticLaunchCompletion();
}

// ---------------------------------------------------------------------------
// Kernel 4: broadcast fv over N. 1024 blocks x 256 threads, fv in a register,
// 16 coalesced STG.128 each (at the L2 write-throughput floor).
// ---------------------------------------------------------------------------
__global__ __launch_bounds__(256) void k_bcast(float4* __restrict__ out) {
    int t = threadIdx.x;
    int bh = blockIdx.x >> 5;          // b*2 + half  (0..31)
    int seg = blockIdx.x & 31;         // 32 segments of 4096 float4
    float4* dst = out + (size_t)bh * 131072 + (size_t)seg * 4096;   // pre-sync

    cudaGridDependencySynchronize();   // g_fv ready

    float4 v = __ldg((const float4*)g_fv + (size_t)bh * 32 + (t & 31));
#pragma unroll
    for (int k = 0; k < 16; ++k)
        __stcs(dst + k * 256 + t, v);  // channel (addr%32) matches t%32
}

// ---------------------------------------------------------------------------
extern "C" void kernel_launch(void* const* d_in, const int* in_sizes, int n_in,
                              void* d_out, int out_size) {
    const float* x   = (const float*)d_in[0];
    const float* Wk  = (const float*)d_in[1];
    const float* Wv  = (const float*)d_in[2];
    const float* Wp  = (const float*)d_in[3];
    const float* bp  = (const float*)d_in[4];
    const float* mem = (const float*)d_in[5];
    float4* out = (float4*)d_out;

    k_prep_u<<<1, 256>>>(Wk, mem);

    cudaLaunchAttribute at[1];
    at[0].id = cudaLaunchAttributeProgrammaticStreamSerialization;
    at[0].val.programmaticStreamSerializationAllowed = 1;

    cudaLaunchConfig_t cfg = {};
    cfg.stream = 0;                    // legacy default stream (same as <<<>>>)
    cfg.attrs = at;
    cfg.numAttrs = 1;

    cfg.gridDim = dim3(NB * NCH);
    cfg.blockDim = dim3(128);
    cudaLaunchKernelEx(&cfg, k_fused, x);

    cfg.gridDim = dim3(32);
    cfg.blockDim = dim3(1024);
    cudaLaunchKernelEx(&cfg, k_final, Wv, Wp, bp);

    cfg.gridDim = dim3(1024);
    cfg.blockDim = dim3(256);
    cudaLaunchKernelEx(&cfg, k_bcast, out);
}